// round 4
// baseline (speedup 1.0000x reference)
#include <cuda_runtime.h>
#include <cstdint>

#define SEQ    512
#define INSZ   4096
#define HID    2048
#define OUTSZ  4096
#define STEPS  30
#define G3     6144   // 3*HID

#define NB     128    // persistent CTAs (<=148 SMs, all resident)
#define NT     256
#define UPB    16     // hidden units per block  (2048/128)
#define RPB    48     // gate rows per block     (3*UPB)
#define ORPB   32     // output rows per block   (4096/128)

// ---------------- device globals (scratch; no runtime allocation) -----------
__device__ float               g_GI[SEQ * G3];     // precomputed Wih@x + bih
__device__ float               g_h[2][HID];        // double-buffered hidden state
__device__ unsigned            g_arrive[NB];
__device__ unsigned            g_release;
__device__ unsigned long long  g_amax[STEPS];
__device__ float               g_sumexp[STEPS];

// ---------------- helpers ---------------------------------------------------
__device__ __forceinline__ float warp_sum(float v) {
#pragma unroll
    for (int o = 16; o; o >>= 1) v += __shfl_xor_sync(0xffffffffu, v, o);
    return v;
}

__device__ __forceinline__ float sigmoidf_(float x) {
    return 1.0f / (1.0f + expf(-x));
}

// Grid-wide barrier: monotonic per-CTA flags + single release counter.
// Works across launches because every launch performs the same number of
// barriers on every CTA, so all counters are equal at launch start and
// `base` is captured before any flag can change.
__device__ __forceinline__ void grid_bar(int bid, unsigned base, unsigned* kbar) {
    unsigned k = ++(*kbar);
    __threadfence();          // make this thread's prior global writes visible
    __syncthreads();
    if (threadIdx.x == 0) {
        *(volatile unsigned*)&g_arrive[bid] = base + k;
    }
    if (bid == 0 && threadIdx.x < 32) {
        for (;;) {
            unsigned mn = 0xFFFFFFFFu;
            for (int i = (int)threadIdx.x; i < NB; i += 32) {
                unsigned d = (*(volatile unsigned*)&g_arrive[i]) - base;
                mn = mn < d ? mn : d;
            }
#pragma unroll
            for (int o = 16; o; o >>= 1) {
                unsigned other = __shfl_xor_sync(0xffffffffu, mn, o);
                mn = mn < other ? mn : other;
            }
            if (mn >= k) break;
        }
        if (threadIdx.x == 0) {
            __threadfence();
            *(volatile unsigned*)&g_release = base + k;
        }
    }
    if (threadIdx.x == 0) {
        while ((*(volatile unsigned*)&g_release) - base < k) {}
    }
    __syncthreads();
    __threadfence();          // acquire side
}

// Load hidden state (written by other SMs) into shared memory, bypassing L1.
__device__ __forceinline__ void load_h(const float* hsrc, float* hs, int tid) {
#pragma unroll
    for (int i = 0; i < HID / (NT * 4); i++) {   // 2 iterations
        int idx = (tid + i * NT) * 4;
        float4 v = __ldcg((const float4*)(hsrc + idx));
        *(float4*)&hs[idx] = v;
    }
}

// 48-row x 2048 matvec: warp w handles rows w*6..w*6+5; result -> gh_s[48].
__device__ __forceinline__ void matvec48(const float* __restrict__ W,
                                         const float* __restrict__ bias,
                                         const float* hs, float* gh_s,
                                         int bid, int tid) {
    int warp = tid >> 5, lane = tid & 31;
#pragma unroll
    for (int rr = 0; rr < 6; rr++) {
        int r48  = warp * 6 + rr;
        int gate = r48 >> 4;
        int grow = gate * HID + bid * UPB + (r48 & 15);
        const float4* wrow = (const float4*)(W + (size_t)grow * HID);
        float acc = 0.f;
#pragma unroll
        for (int kk = 0; kk < 16; kk++) {
            float4 w4 = __ldg(&wrow[lane + kk * 32]);
            const float4 h4 = *(const float4*)&hs[(lane + kk * 32) * 4];
            acc += w4.x * h4.x + w4.y * h4.y + w4.z * h4.z + w4.w * h4.w;
        }
        acc = warp_sum(acc);
        if (lane == 0) gh_s[r48] = acc + bias[grow];
    }
}

// ---------------- kernel 1: GI = X @ Wih^T + bih ----------------------------
// C[m,n] = sum_k X[m,k] * Wih[n,k];  M=512, N=6144, K=4096
__global__ void __launch_bounds__(256) gemm_gi_kernel(
    const float* __restrict__ X, const float* __restrict__ W,
    const float* __restrict__ bih) {
    __shared__ float As[8][132];   // [k][m], padded
    __shared__ float Bs[8][132];   // [k][n], padded

    int tid = threadIdx.x;
    int m0 = blockIdx.y * 128, n0 = blockIdx.x * 128;
    int lr = tid >> 1;             // 0..127
    int lk = (tid & 1) * 4;        // 0 or 4
    const float* Aptr = X + (size_t)(m0 + lr) * INSZ + lk;
    const float* Bptr = W + (size_t)(n0 + lr) * INSZ + lk;

    int tx = tid & 15, ty = tid >> 4;
    float acc[8][8];
#pragma unroll
    for (int i = 0; i < 8; i++)
#pragma unroll
        for (int j = 0; j < 8; j++) acc[i][j] = 0.f;

    for (int k0 = 0; k0 < INSZ; k0 += 8) {
        float4 a4 = *(const float4*)(Aptr + k0);
        float4 b4 = *(const float4*)(Bptr + k0);
        __syncthreads();
        As[lk + 0][lr] = a4.x; As[lk + 1][lr] = a4.y;
        As[lk + 2][lr] = a4.z; As[lk + 3][lr] = a4.w;
        Bs[lk + 0][lr] = b4.x; Bs[lk + 1][lr] = b4.y;
        Bs[lk + 2][lr] = b4.z; Bs[lk + 3][lr] = b4.w;
        __syncthreads();
#pragma unroll
        for (int kk = 0; kk < 8; kk++) {
            float a[8], b[8];
            *(float4*)(a)     = *(const float4*)&As[kk][ty * 4];
            *(float4*)(a + 4) = *(const float4*)&As[kk][ty * 4 + 64];
            *(float4*)(b)     = *(const float4*)&Bs[kk][tx * 4];
            *(float4*)(b + 4) = *(const float4*)&Bs[kk][tx * 4 + 64];
#pragma unroll
            for (int i = 0; i < 8; i++)
#pragma unroll
                for (int j = 0; j < 8; j++) acc[i][j] += a[i] * b[j];
        }
    }

#pragma unroll
    for (int ih = 0; ih < 2; ih++)
#pragma unroll
        for (int i = 0; i < 4; i++) {
            int m = m0 + ih * 64 + ty * 4 + i;
#pragma unroll
            for (int jh = 0; jh < 2; jh++) {
                int n = n0 + jh * 64 + tx * 4;
                float4 v;
                v.x = acc[ih * 4 + i][jh * 4 + 0] + bih[n + 0];
                v.y = acc[ih * 4 + i][jh * 4 + 1] + bih[n + 1];
                v.z = acc[ih * 4 + i][jh * 4 + 2] + bih[n + 2];
                v.w = acc[ih * 4 + i][jh * 4 + 3] + bih[n + 3];
                *(float4*)&g_GI[(size_t)m * G3 + n] = v;
            }
        }
}

// ---------------- kernel 2: persistent encoder + decoder --------------------
__global__ void __launch_bounds__(NT, 1) rnn_kernel(
    const float* __restrict__ enc_Whh, const float* __restrict__ enc_bhh,
    const float* __restrict__ dec_Wih, const float* __restrict__ dec_Whh,
    const float* __restrict__ dec_bih, const float* __restrict__ dec_bhh,
    const float* __restrict__ W_out,   const float* __restrict__ b_out,
    float* __restrict__ out) {

    int bid = blockIdx.x, tid = threadIdx.x;
    __shared__ float hs[HID];
    __shared__ float gh_s[RPB];
    __shared__ float gi_s[RPB];
    __shared__ float ls[ORPB];

    unsigned base = *(volatile unsigned*)&g_release;   // stable at launch start
    unsigned kbar = 0;

    // per-launch re-init
    if (tid < UPB) __stcg(&g_h[0][bid * UPB + tid], 0.f);
    if (bid == 0 && tid < STEPS) {
        g_amax[tid]   = 0ull;
        g_sumexp[tid] = 0.f;
    }
    grid_bar(bid, base, &kbar);

    int cur = 0;

    // ---------------- encoder: 512 sequential GRU steps ----------------
    for (int t = 0; t < SEQ; t++) {
        load_h(g_h[cur], hs, tid);
        __syncthreads();
        matvec48(enc_Whh, enc_bhh, hs, gh_s, bid, tid);
        __syncthreads();
        if (tid < UPB) {
            int u = bid * UPB + tid;
            const float* gi = g_GI + (size_t)t * G3;
            float r = sigmoidf_(gi[u]            + gh_s[tid]);
            float z = sigmoidf_(gi[HID + u]      + gh_s[UPB + tid]);
            float n = tanhf(    gi[2 * HID + u]  + r * gh_s[2 * UPB + tid]);
            __stcg(&g_h[cur ^ 1][u], (1.f - z) * n + z * hs[u]);
        }
        cur ^= 1;
        grid_bar(bid, base, &kbar);
    }

    // ---------------- decoder: 30 greedy steps ----------------
    int prev_idx = -1;     // first x is the zero vector
    for (int s = 0; s < STEPS; s++) {
        load_h(g_h[cur], hs, tid);
        if (tid < RPB) {                       // gi = Wih[:,onehot] + bih
            int gate = tid >> 4;
            int grow = gate * HID + bid * UPB + (tid & 15);
            float v = dec_bih[grow];
            if (prev_idx >= 0) v += dec_Wih[(size_t)grow * INSZ + prev_idx];
            gi_s[tid] = v;
        }
        __syncthreads();
        matvec48(dec_Whh, dec_bhh, hs, gh_s, bid, tid);
        __syncthreads();
        if (tid < UPB) {
            int u = bid * UPB + tid;
            float r = sigmoidf_(gi_s[tid]           + gh_s[tid]);
            float z = sigmoidf_(gi_s[UPB + tid]     + gh_s[UPB + tid]);
            float n = tanhf(    gi_s[2 * UPB + tid] + r * gh_s[2 * UPB + tid]);
            __stcg(&g_h[cur ^ 1][u], (1.f - z) * n + z * hs[u]);
        }
        cur ^= 1;
        grid_bar(bid, base, &kbar);           // B1: h_new visible everywhere

        // logits for this CTA's 32 output rows
        load_h(g_h[cur], hs, tid);
        __syncthreads();
        {
            int warp = tid >> 5, lane = tid & 31;
#pragma unroll
            for (int rr = 0; rr < 4; rr++) {
                int rl = warp * 4 + rr;
                int grow = bid * ORPB + rl;
                const float4* wrow = (const float4*)(W_out + (size_t)grow * HID);
                float acc = 0.f;
#pragma unroll
                for (int kk = 0; kk < 16; kk++) {
                    float4 w4 = __ldg(&wrow[lane + kk * 32]);
                    const float4 h4 = *(const float4*)&hs[(lane + kk * 32) * 4];
                    acc += w4.x * h4.x + w4.y * h4.y + w4.z * h4.z + w4.w * h4.w;
                }
                acc = warp_sum(acc);
                if (lane == 0) ls[rl] = acc + b_out[grow];
            }
        }
        __syncthreads();

        // global (max, argmax) via packed atomicMax; first-index tie-break
        if (tid < 32) {
            float v = ls[tid];
            unsigned sb = __float_as_uint(v);
            sb = (sb & 0x80000000u) ? ~sb : (sb | 0x80000000u);
            unsigned long long pack =
                ((unsigned long long)sb << 32) |
                (unsigned long long)(0xFFFFFFFFu - (unsigned)(bid * ORPB + tid));
#pragma unroll
            for (int o = 16; o; o >>= 1) {
                unsigned long long other = __shfl_xor_sync(0xffffffffu, pack, o);
                pack = other > pack ? other : pack;
            }
            if (tid == 0) atomicMax(&g_amax[s], pack);
        }
        grid_bar(bid, base, &kbar);           // B2: global max ready

        unsigned long long pk = *(volatile unsigned long long*)&g_amax[s];
        unsigned hi = (unsigned)(pk >> 32);
        float gmax = __uint_as_float((hi & 0x80000000u) ? (hi & 0x7FFFFFFFu) : ~hi);

        if (tid < 32) {
            float e = expf(ls[tid] - gmax);
            e = warp_sum(e);
            if (tid == 0) atomicAdd(&g_sumexp[s], e);
        }
        grid_bar(bid, base, &kbar);           // B3: global sumexp ready

        float lse = logf(*(volatile float*)&g_sumexp[s]);
        if (tid < 32)
            out[(size_t)s * OUTSZ + bid * ORPB + tid] = ls[tid] - gmax - lse;
        prev_idx = (int)(0xFFFFFFFFu - (unsigned)(pk & 0xFFFFFFFFull));
    }
}

// ---------------- launch ----------------------------------------------------
extern "C" void kernel_launch(void* const* d_in, const int* in_sizes, int n_in,
                              void* d_out, int out_size) {
    const float* input   = (const float*)d_in[0];
    const float* enc_Wih = (const float*)d_in[1];
    const float* enc_Whh = (const float*)d_in[2];
    const float* enc_bih = (const float*)d_in[3];
    const float* enc_bhh = (const float*)d_in[4];
    const float* dec_Wih = (const float*)d_in[5];
    const float* dec_Whh = (const float*)d_in[6];
    const float* dec_bih = (const float*)d_in[7];
    const float* dec_bhh = (const float*)d_in[8];
    const float* W_out   = (const float*)d_in[9];
    const float* b_out   = (const float*)d_in[10];
    float* out = (float*)d_out;

    dim3 g1(G3 / 128, SEQ / 128);   // 48 x 4
    gemm_gi_kernel<<<g1, 256>>>(input, enc_Wih, enc_bih);
    rnn_kernel<<<NB, NT>>>(enc_Whh, enc_bhh, dec_Wih, dec_Whh,
                           dec_bih, dec_bhh, W_out, b_out, out);
}